// round 3
// baseline (speedup 1.0000x reference)
#include <cuda_runtime.h>
#include <cuda_bf16.h>

// NeighborListForTraining: all intra-molecule ordered pairs (i!=j) for
// 2000 molecules x 64 atoms. Output (float32, concatenated flat):
//   [0,P) i_idx | [P,2P) j_idx | [2P,3P) d_ij | [3P,6P) r_ij[P][3]
// P = n_mols * 64*63 = 8,064,000.
//
// R3: kill 4-way LDS bank conflicts (R2 ncu: L1=73.9% dominated by conflicted
// scalar LDS). Positions now stored as float4/atom in SMEM with an XOR bank
// swizzle so the lane-step-4 access pattern hits all 8 16B banks -> LDS.128
// conflict-free. Stores stay float4 streaming (.cs).

#define NPM   64
#define PPM   (NPM * (NPM - 1))    // 4032 pairs per molecule
#define GPM   (PPM / 4)            // 1008 groups of 4 pairs
#define CUTOFF 5.0f
#define BLOCK 256

// Swizzled slot for atom a: permutes low 3 bits by XOR with bits [5:3].
// bank16(slot) = (a&7) ^ ((a>>3)&7): lane-step-4 in `a` then covers all
// 8 distinct 16B banks across each 8-lane phase of an LDS.128.
__device__ __forceinline__ int swz(int a) {
    return (a & ~7) | ((a ^ (a >> 3)) & 7);
}

__device__ __forceinline__ void stcs4(float* p, float4 v) {
    __stcs((float4*)p, v);
}

__global__ __launch_bounds__(BLOCK) void neighborlist_kernel(
    const float* __restrict__ pos,   // [n_atoms, 3]
    float* __restrict__ out,
    int n_mols)
{
    __shared__ float4 s_pos[NPM];

    const int mol = blockIdx.x;
    const float* mp = pos + (size_t)mol * (NPM * 3);

    // Stage this molecule's 64 positions into swizzled float4 slots.
    if (threadIdx.x < NPM) {
        const int a = threadIdx.x;
        s_pos[swz(a)] = make_float4(mp[3 * a + 0], mp[3 * a + 1],
                                    mp[3 * a + 2], 0.0f);
    }
    __syncthreads();

    const long long P = (long long)n_mols * PPM;
    float* __restrict__ out_i = out;
    float* __restrict__ out_j = out + P;
    float* __restrict__ out_d = out + 2 * P;
    float* __restrict__ out_r = out + 3 * P;

    const int atom_base = mol * NPM;
    const long long mol_pair_base = (long long)mol * PPM;

    for (int g = threadIdx.x; g < GPM; g += BLOCK) {
        const int pbase = g * 4;   // local pair index of first pair in group

        float4 fi, fj, fd;
        float  rr[12];
        float* fip = (float*)&fi;
        float* fjp = (float*)&fj;
        float* fdp = (float*)&fd;

        #pragma unroll
        for (int k = 0; k < 4; k++) {
            const int t  = pbase + k;          // 0..4031
            const int il = t / 63;             // i_loc
            const int rm = t - il * 63;
            const int jl = rm + (rm >= il);    // j_loc, skipping i

            const float4 pi = s_pos[swz(il)];  // near-uniform -> broadcast
            const float4 pj = s_pos[swz(jl)];  // conflict-free via swizzle

            float dx = pj.x - pi.x;
            float dy = pj.y - pi.y;
            float dz = pj.z - pi.z;
            float d  = sqrtf(dx * dx + dy * dy + dz * dz);

            const bool in_cut = (d <= CUTOFF);
            if (!in_cut) { d = 0.0f; dx = 0.0f; dy = 0.0f; dz = 0.0f; }

            fip[k] = (float)(atom_base + il);
            fjp[k] = (float)(atom_base + jl);
            fdp[k] = d;
            rr[3 * k + 0] = dx;
            rr[3 * k + 1] = dy;
            rr[3 * k + 2] = dz;
        }

        const long long p = mol_pair_base + pbase;   // p % 4 == 0
        stcs4(out_i + p, fi);
        stcs4(out_j + p, fj);
        stcs4(out_d + p, fd);

        float* orr = out_r + 3 * p;                  // 3p % 4 == 0
        stcs4(orr + 0, *(float4*)(rr + 0));
        stcs4(orr + 4, *(float4*)(rr + 4));
        stcs4(orr + 8, *(float4*)(rr + 8));
    }
}

extern "C" void kernel_launch(void* const* d_in, const int* in_sizes, int n_in,
                              void* d_out, int out_size)
{
    const float* positions = (const float*)d_in[0];
    const int n_atoms = in_sizes[0] / 3;
    const int n_mols  = n_atoms / NPM;

    float* out = (float*)d_out;
    neighborlist_kernel<<<n_mols, BLOCK>>>(positions, out, n_mols);
}